// round 7
// baseline (speedup 1.0000x reference)
#include <cuda_runtime.h>
#include <math.h>

#define BB 2048
#define SS 512
#define HH 256
#define FF 64
#define G3 (3 * HH)    // 768

// ---------------- scratch ----------------
__device__ float g_logits[BB * SS];    // [B, 512]
__device__ float g_ctx[BB * HH];       // [B, 256]
__device__ float g_gh[BB * G3];        // [B, 768]

// ---------------- K1: logits GEMM, 32x64 tiles, fused concat (512 blocks) ----------------
__global__ __launch_bounds__(256)
void k1_logits(const float* __restrict__ ph, const float* __restrict__ y,
               const float* __restrict__ attn_W, const float* __restrict__ attn_b,
               float* __restrict__ logits) {
    __shared__ __align__(16) float As[16 * 36];   // [k][batch row], 32 rows
    __shared__ __align__(16) float Ws[16 * 68];   // [k][n row], 64 rows

    const int bn = (blockIdx.x & 7) * 64;
    const int bm = (blockIdx.x >> 3) * 32;
    const int tid = threadIdx.x;
    const int tx = tid & 15;
    const int ty = tid >> 4;

    float acc[2][4];
#pragma unroll
    for (int i = 0; i < 2; i++)
#pragma unroll
        for (int j = 0; j < 4; j++) acc[i][j] = 0.0f;

    for (int k0 = 0; k0 < 320; k0 += 16) {
#pragma unroll
        for (int j = 0; j < 2; j++) {
            int i = tid + 256 * j;           // 0..511
            int r = i >> 4, c = i & 15;      // r: 0..31
            int k = k0 + c;
            As[c * 36 + r] = (k < 256) ? ph[(size_t)(bm + r) * 256 + k]
                                       : y[(size_t)(bm + r) * 64 + (k - 256)];
        }
#pragma unroll
        for (int j = 0; j < 4; j++) {
            int i = tid + 256 * j;           // 0..1023
            int r = i >> 4, c = i & 15;      // r: 0..63
            Ws[c * 68 + r] = attn_W[(size_t)(bn + r) * 320 + k0 + c];
        }
        __syncthreads();

#pragma unroll
        for (int kk = 0; kk < 16; kk++) {
            float2 a2 = *reinterpret_cast<const float2*>(&As[kk * 36 + ty * 2]);
            float4 w4 = *reinterpret_cast<const float4*>(&Ws[kk * 68 + tx * 4]);
            float av[2] = {a2.x, a2.y};
            float wv[4] = {w4.x, w4.y, w4.z, w4.w};
#pragma unroll
            for (int i = 0; i < 2; i++)
#pragma unroll
                for (int j = 0; j < 4; j++) acc[i][j] = fmaf(av[i], wv[j], acc[i][j]);
        }
        __syncthreads();
    }

#pragma unroll
    for (int i = 0; i < 2; i++) {
        int m = bm + ty * 2 + i;
#pragma unroll
        for (int j = 0; j < 4; j++) {
            int n = bn + tx * 4 + j;
            logits[(size_t)m * SS + n] = acc[i][j] + attn_b[n];
        }
    }
}

// ---------------- K2: gh-GEMM (compute) overlapped with softmax+ctx (HBM stream) ----------------
// blocks [0,384): gh GEMM; [384,392): init d_out; [392, 392+2048): softmax_ctx.
union SmemK2 {
    struct { float As[16 * 68]; float Ws[16 * 68]; } gemm;
    struct { float w[SS]; float red[8]; float4 part[256]; } sm;
};

__device__ __forceinline__ void gh_gemm_tile(float* __restrict__ As, float* __restrict__ Ws,
                                             int bm, int bn,
                                             const float* __restrict__ A,
                                             const float* __restrict__ W,
                                             const float* __restrict__ bias,
                                             float* __restrict__ C) {
    const int tid = threadIdx.x;
    const int tx = tid & 15;
    const int ty = tid >> 4;

    float acc[4][4];
#pragma unroll
    for (int i = 0; i < 4; i++)
#pragma unroll
        for (int j = 0; j < 4; j++) acc[i][j] = 0.0f;

    for (int k0 = 0; k0 < 256; k0 += 16) {
#pragma unroll
        for (int j = 0; j < 4; j++) {
            int i = tid + 256 * j;
            int r = i >> 4, c = i & 15;
            As[c * 68 + r] = A[(size_t)(bm + r) * 256 + k0 + c];
            Ws[c * 68 + r] = W[(size_t)(bn + r) * 256 + k0 + c];
        }
        __syncthreads();

#pragma unroll
        for (int kk = 0; kk < 16; kk++) {
            float4 a4 = *reinterpret_cast<const float4*>(&As[kk * 68 + ty * 4]);
            float4 w4 = *reinterpret_cast<const float4*>(&Ws[kk * 68 + tx * 4]);
            float av[4] = {a4.x, a4.y, a4.z, a4.w};
            float wv[4] = {w4.x, w4.y, w4.z, w4.w};
#pragma unroll
            for (int i = 0; i < 4; i++)
#pragma unroll
                for (int j = 0; j < 4; j++) acc[i][j] = fmaf(av[i], wv[j], acc[i][j]);
        }
        __syncthreads();
    }

#pragma unroll
    for (int i = 0; i < 4; i++) {
        int m = bm + ty * 4 + i;
#pragma unroll
        for (int j = 0; j < 4; j++) {
            int n = bn + tx * 4 + j;
            C[(size_t)m * G3 + n] = acc[i][j] + bias[n];
        }
    }
}

__device__ __forceinline__ void softmax_ctx_body(SmemK2& s, int b,
                                                 const float* __restrict__ logits,
                                                 const float* __restrict__ enc,
                                                 float* __restrict__ ctx) {
    const int t = threadIdx.x;

    float v0 = logits[(size_t)b * SS + t];
    float v1 = logits[(size_t)b * SS + 256 + t];

    float mx = fmaxf(v0, v1);
#pragma unroll
    for (int o = 16; o; o >>= 1) mx = fmaxf(mx, __shfl_xor_sync(0xffffffffu, mx, o));
    if ((t & 31) == 0) s.sm.red[t >> 5] = mx;
    __syncthreads();
    mx = fmaxf(fmaxf(fmaxf(s.sm.red[0], s.sm.red[1]), fmaxf(s.sm.red[2], s.sm.red[3])),
               fmaxf(fmaxf(s.sm.red[4], s.sm.red[5]), fmaxf(s.sm.red[6], s.sm.red[7])));
    __syncthreads();

    float e0 = __expf(v0 - mx);
    float e1 = __expf(v1 - mx);
    s.sm.w[t] = e0;
    s.sm.w[t + 256] = e1;

    float smv = e0 + e1;
#pragma unroll
    for (int o = 16; o; o >>= 1) smv += __shfl_xor_sync(0xffffffffu, smv, o);
    if ((t & 31) == 0) s.sm.red[t >> 5] = smv;
    __syncthreads();
    float inv = 1.0f / (s.sm.red[0] + s.sm.red[1] + s.sm.red[2] + s.sm.red[3] +
                        s.sm.red[4] + s.sm.red[5] + s.sm.red[6] + s.sm.red[7]);

    const float4* ep = reinterpret_cast<const float4*>(enc + (size_t)b * SS * HH);
    const int hq = t & 63;
    const int sr = t >> 6;
    float4 acc = make_float4(0.f, 0.f, 0.f, 0.f);

    for (int s0 = 0; s0 < SS; s0 += 32) {
#pragma unroll
        for (int u = 0; u < 8; u++) {
            int row = s0 + u * 4 + sr;
            float4 v = __ldcs(&ep[(size_t)row * 64 + hq]);
            float ww = s.sm.w[row];
            acc.x = fmaf(ww, v.x, acc.x);
            acc.y = fmaf(ww, v.y, acc.y);
            acc.z = fmaf(ww, v.z, acc.z);
            acc.w = fmaf(ww, v.w, acc.w);
        }
    }

    s.sm.part[t] = acc;
    __syncthreads();
    if (t < 64) {
        float4 a = s.sm.part[t], b4 = s.sm.part[t + 64];
        float4 c4 = s.sm.part[t + 128], d4 = s.sm.part[t + 192];
        float4 r;
        r.x = (a.x + b4.x + c4.x + d4.x) * inv;
        r.y = (a.y + b4.y + c4.y + d4.y) * inv;
        r.z = (a.z + b4.z + c4.z + d4.z) * inv;
        r.w = (a.w + b4.w + c4.w + d4.w) * inv;
        *reinterpret_cast<float4*>(&ctx[(size_t)b * HH + t * 4]) = r;
    }
}

__global__ __launch_bounds__(256)
void k2_stream_gemm(const float* __restrict__ logits, const float* __restrict__ enc,
                    const float* __restrict__ ph,
                    const float* __restrict__ W_hh, const float* __restrict__ b_hh,
                    const float* __restrict__ out_b,
                    float* __restrict__ ctx, float* __restrict__ gh,
                    float* __restrict__ d_out) {
    __shared__ __align__(16) SmemK2 s;
    const int bid = blockIdx.x;
    if (bid < 384) {
        int bn = (bid % 12) * 64;
        int bm = (bid / 12) * 64;
        gh_gemm_tile(s.gemm.As, s.gemm.Ws, bm, bn, ph, W_hh, b_hh, gh);
    } else if (bid < 392) {
        int i = (bid - 384) * 256 + threadIdx.x;
        d_out[i] = out_b[0];
    } else {
        softmax_ctx_body(s, bid - 392, logits, enc, ctx);
    }
}

// ---------------- K3: gi GEMM (3 gates, 32x32 tile) + GRU + h_new + out (512 blocks) ----------------
// grid(8, 64): x = hidden tile (32 of 256), y = batch tile (32 of 2048). 256 threads.
__global__ __launch_bounds__(256)
void k3_gru_kernel(const float* __restrict__ ctx,
                   const float* __restrict__ W_ih, const float* __restrict__ b_ih,
                   const float* __restrict__ gh,  const float* __restrict__ ph,
                   const float* __restrict__ outW, float* __restrict__ d_out) {
    __shared__ __align__(16) float As[16 * 36];        // ctx tile [k][b], 32 rows
    __shared__ __align__(16) float Ws[3][16 * 36];     // W_ih tiles per gate [k][h], 32 rows

    const int bm = blockIdx.y * 32;   // batch base
    const int bh = blockIdx.x * 32;   // hidden base
    const int tid = threadIdx.x;
    const int tx = tid & 15;          // hidden pair index
    const int ty = tid >> 4;          // owns 2 batch rows

    float acc[2][2][3];
#pragma unroll
    for (int i = 0; i < 2; i++)
#pragma unroll
        for (int j = 0; j < 2; j++)
#pragma unroll
            for (int g = 0; g < 3; g++) acc[i][j][g] = 0.0f;

    for (int k0 = 0; k0 < HH; k0 += 16) {
#pragma unroll
        for (int j = 0; j < 2; j++) {
            int i = tid + 256 * j;          // 0..511
            int r = i >> 4, c = i & 15;     // r: 0..31
            As[c * 36 + r] = ctx[(size_t)(bm + r) * HH + k0 + c];
        }
#pragma unroll
        for (int j = 0; j < 6; j++) {
            int i = tid + 256 * j;          // 0..1535
            int r = i >> 4, c = i & 15;     // r: 0..95
            int g = r >> 5, rr = r & 31;
            Ws[g][c * 36 + rr] = W_ih[(size_t)(g * HH + bh + rr) * HH + k0 + c];
        }
        __syncthreads();

#pragma unroll
        for (int kk = 0; kk < 16; kk++) {
            float2 a2 = *reinterpret_cast<const float2*>(&As[kk * 36 + ty * 2]);
            float av[2] = {a2.x, a2.y};
#pragma unroll
            for (int g = 0; g < 3; g++) {
                float2 w2 = *reinterpret_cast<const float2*>(&Ws[g][kk * 36 + tx * 2]);
                float wv[2] = {w2.x, w2.y};
#pragma unroll
                for (int i = 0; i < 2; i++)
#pragma unroll
                    for (int j = 0; j < 2; j++)
                        acc[i][j][g] = fmaf(av[i], wv[j], acc[i][j][g]);
            }
        }
        __syncthreads();
    }

    // epilogue: gates, h_new, out projection
#pragma unroll
    for (int i = 0; i < 2; i++) {
        const int b = bm + ty * 2 + i;
        const float* ghb = gh + (size_t)b * G3;
        float p = 0.0f;
#pragma unroll
        for (int j = 0; j < 2; j++) {
            const int h = bh + tx * 2 + j;
            float gir = acc[i][j][0] + b_ih[h];
            float giz = acc[i][j][1] + b_ih[h + 256];
            float gin = acc[i][j][2] + b_ih[h + 512];
            float r = 1.0f / (1.0f + __expf(-(gir + ghb[h])));
            float z = 1.0f / (1.0f + __expf(-(giz + ghb[h + 256])));
            float n = tanhf(gin + r * ghb[h + 512]);
            float hv = (1.0f - z) * n + z * ph[(size_t)b * HH + h];
            d_out[BB + (size_t)b * HH + h] = hv;
            p = fmaf(hv, outW[h], p);
        }
        // reduce across the 16 tx lanes sharing this batch row
        p += __shfl_xor_sync(0xffffffffu, p, 1);
        p += __shfl_xor_sync(0xffffffffu, p, 2);
        p += __shfl_xor_sync(0xffffffffu, p, 4);
        p += __shfl_xor_sync(0xffffffffu, p, 8);
        if (tx == 0) atomicAdd(&d_out[b], p);
    }
}

// ---------------- launcher ----------------
extern "C" void kernel_launch(void* const* d_in, const int* in_sizes, int n_in,
                              void* d_out, int out_size) {
    const float* enc    = (const float*)d_in[0];
    const float* ph     = (const float*)d_in[1];
    const float* y      = (const float*)d_in[2];
    const float* attn_W = (const float*)d_in[3];
    const float* attn_b = (const float*)d_in[4];
    const float* W_ih   = (const float*)d_in[5];
    const float* W_hh   = (const float*)d_in[6];
    const float* b_ih   = (const float*)d_in[7];
    const float* b_hh   = (const float*)d_in[8];
    const float* out_W  = (const float*)d_in[9];
    const float* out_b  = (const float*)d_in[10];
    float* out = (float*)d_out;

    float *logits = nullptr, *ctx = nullptr, *gh = nullptr;
    cudaGetSymbolAddress((void**)&logits, g_logits);
    cudaGetSymbolAddress((void**)&ctx,    g_ctx);
    cudaGetSymbolAddress((void**)&gh,     g_gh);

    k1_logits<<<512, 256>>>(ph, y, attn_W, attn_b, logits);
    k2_stream_gemm<<<392 + BB, 256>>>(logits, enc, ph, W_hh, b_hh, out_b, ctx, gh, out);
    k3_gru_kernel<<<dim3(8, 64), 256>>>(ctx, W_ih, b_ih, gh, ph, out_W, out);
}

// round 9
// speedup vs baseline: 1.0796x; 1.0796x over previous
#include <cuda_runtime.h>
#include <math.h>

#define BB 2048
#define SS 512
#define HH 256
#define FF 64
#define G3 (3 * HH)    // 768

// ---------------- scratch ----------------
__device__ float g_logits_a[BB * SS];  // partial logits, K 0..159  (+bias)
__device__ float g_logits_b[BB * SS];  // partial logits, K 160..319
__device__ float g_ctx[BB * HH];
__device__ float g_gh[BB * G3];

// ---------------- K1: split-K logits GEMM, 64x64 tiles, fused concat (512 blocks) ----------------
__global__ __launch_bounds__(256)
void k1_logits(const float* __restrict__ ph, const float* __restrict__ y,
               const float* __restrict__ attn_W, const float* __restrict__ attn_b,
               float* __restrict__ la, float* __restrict__ lb) {
    __shared__ __align__(16) float As[16 * 68];
    __shared__ __align__(16) float Ws[16 * 68];

    const int half = (blockIdx.x >= 256);
    const int idx = blockIdx.x & 255;
    const int bn = (idx & 7) * 64;
    const int bm = (idx >> 3) * 64;
    const int kbase = half * 160;
    const int tid = threadIdx.x;
    const int tx = tid & 15;
    const int ty = tid >> 4;

    float acc[4][4];
#pragma unroll
    for (int i = 0; i < 4; i++)
#pragma unroll
        for (int j = 0; j < 4; j++) acc[i][j] = 0.0f;

    for (int k0 = 0; k0 < 160; k0 += 16) {
#pragma unroll
        for (int j = 0; j < 4; j++) {
            int i = tid + 256 * j;
            int r = i >> 4, c = i & 15;
            int k = kbase + k0 + c;
            As[c * 68 + r] = (k < 256) ? ph[(size_t)(bm + r) * 256 + k]
                                       : y[(size_t)(bm + r) * 64 + (k - 256)];
            Ws[c * 68 + r] = attn_W[(size_t)(bn + r) * 320 + k];
        }
        __syncthreads();

#pragma unroll
        for (int kk = 0; kk < 16; kk++) {
            float4 a4 = *reinterpret_cast<const float4*>(&As[kk * 68 + ty * 4]);
            float4 w4 = *reinterpret_cast<const float4*>(&Ws[kk * 68 + tx * 4]);
            float av[4] = {a4.x, a4.y, a4.z, a4.w};
            float wv[4] = {w4.x, w4.y, w4.z, w4.w};
#pragma unroll
            for (int i = 0; i < 4; i++)
#pragma unroll
                for (int j = 0; j < 4; j++) acc[i][j] = fmaf(av[i], wv[j], acc[i][j]);
        }
        __syncthreads();
    }

    float* C = half ? lb : la;
#pragma unroll
    for (int i = 0; i < 4; i++) {
        int m = bm + ty * 4 + i;
#pragma unroll
        for (int j = 0; j < 4; j++) {
            int n = bn + tx * 4 + j;
            float b = half ? 0.0f : attn_b[n];
            C[(size_t)m * SS + n] = acc[i][j] + b;
        }
    }
}

// ---------------- K2: single-wave persistent stream + gh GEMM + init ----------------
// blocks [0,96): gh GEMM, 4 bm tiles each (384 tiles total = full 2048x768);
// [96,98): init d_out; [98,610): softmax_ctx, 4 batches each (strided by 512).
union SmemK2 {
    struct { float As[16 * 68]; float Ws[16 * 68]; } gemm;
    struct { float w[SS]; float red[8]; float4 part[256]; } sm;
};

__device__ __forceinline__ void gh_gemm_tile(float* __restrict__ As, float* __restrict__ Ws,
                                             int bm, int bn,
                                             const float* __restrict__ A,
                                             const float* __restrict__ W,
                                             const float* __restrict__ bias,
                                             float* __restrict__ C) {
    const int tid = threadIdx.x;
    const int tx = tid & 15;
    const int ty = tid >> 4;

    float acc[4][4];
#pragma unroll
    for (int i = 0; i < 4; i++)
#pragma unroll
        for (int j = 0; j < 4; j++) acc[i][j] = 0.0f;

    for (int k0 = 0; k0 < 256; k0 += 16) {
#pragma unroll
        for (int j = 0; j < 4; j++) {
            int i = tid + 256 * j;
            int r = i >> 4, c = i & 15;
            As[c * 68 + r] = A[(size_t)(bm + r) * 256 + k0 + c];
            Ws[c * 68 + r] = W[(size_t)(bn + r) * 256 + k0 + c];
        }
        __syncthreads();

#pragma unroll
        for (int kk = 0; kk < 16; kk++) {
            float4 a4 = *reinterpret_cast<const float4*>(&As[kk * 68 + ty * 4]);
            float4 w4 = *reinterpret_cast<const float4*>(&Ws[kk * 68 + tx * 4]);
            float av[4] = {a4.x, a4.y, a4.z, a4.w};
            float wv[4] = {w4.x, w4.y, w4.z, w4.w};
#pragma unroll
            for (int i = 0; i < 4; i++)
#pragma unroll
                for (int j = 0; j < 4; j++) acc[i][j] = fmaf(av[i], wv[j], acc[i][j]);
        }
        __syncthreads();
    }

#pragma unroll
    for (int i = 0; i < 4; i++) {
        int m = bm + ty * 4 + i;
#pragma unroll
        for (int j = 0; j < 4; j++) {
            int n = bn + tx * 4 + j;
            C[(size_t)m * G3 + n] = acc[i][j] + bias[n];
        }
    }
}

__device__ __forceinline__ void softmax_ctx_body(SmemK2& s, int b,
                                                 const float* __restrict__ la,
                                                 const float* __restrict__ lb,
                                                 const float* __restrict__ enc,
                                                 float* __restrict__ ctx) {
    const int t = threadIdx.x;

    float v0 = la[(size_t)b * SS + t]       + lb[(size_t)b * SS + t];
    float v1 = la[(size_t)b * SS + 256 + t] + lb[(size_t)b * SS + 256 + t];

    float mx = fmaxf(v0, v1);
#pragma unroll
    for (int o = 16; o; o >>= 1) mx = fmaxf(mx, __shfl_xor_sync(0xffffffffu, mx, o));
    if ((t & 31) == 0) s.sm.red[t >> 5] = mx;
    __syncthreads();
    mx = fmaxf(fmaxf(fmaxf(s.sm.red[0], s.sm.red[1]), fmaxf(s.sm.red[2], s.sm.red[3])),
               fmaxf(fmaxf(s.sm.red[4], s.sm.red[5]), fmaxf(s.sm.red[6], s.sm.red[7])));
    __syncthreads();

    float e0 = __expf(v0 - mx);
    float e1 = __expf(v1 - mx);
    s.sm.w[t] = e0;
    s.sm.w[t + 256] = e1;

    float smv = e0 + e1;
#pragma unroll
    for (int o = 16; o; o >>= 1) smv += __shfl_xor_sync(0xffffffffu, smv, o);
    if ((t & 31) == 0) s.sm.red[t >> 5] = smv;
    __syncthreads();
    float inv = 1.0f / (s.sm.red[0] + s.sm.red[1] + s.sm.red[2] + s.sm.red[3] +
                        s.sm.red[4] + s.sm.red[5] + s.sm.red[6] + s.sm.red[7]);

    const float4* ep = reinterpret_cast<const float4*>(enc + (size_t)b * SS * HH);
    const int hq = t & 63;
    const int sr = t >> 6;
    float4 acc = make_float4(0.f, 0.f, 0.f, 0.f);

    for (int s0 = 0; s0 < SS; s0 += 32) {
#pragma unroll
        for (int u = 0; u < 8; u++) {
            int row = s0 + u * 4 + sr;
            float4 v = __ldcs(&ep[(size_t)row * 64 + hq]);
            float ww = s.sm.w[row];
            acc.x = fmaf(ww, v.x, acc.x);
            acc.y = fmaf(ww, v.y, acc.y);
            acc.z = fmaf(ww, v.z, acc.z);
            acc.w = fmaf(ww, v.w, acc.w);
        }
    }

    s.sm.part[t] = acc;
    __syncthreads();
    if (t < 64) {
        float4 a = s.sm.part[t], b4 = s.sm.part[t + 64];
        float4 c4 = s.sm.part[t + 128], d4 = s.sm.part[t + 192];
        float4 r;
        r.x = (a.x + b4.x + c4.x + d4.x) * inv;
        r.y = (a.y + b4.y + c4.y + d4.y) * inv;
        r.z = (a.z + b4.z + c4.z + d4.z) * inv;
        r.w = (a.w + b4.w + c4.w + d4.w) * inv;
        *reinterpret_cast<float4*>(&ctx[(size_t)b * HH + t * 4]) = r;
    }
    __syncthreads();   // protect smem reuse across batch iterations
}

__global__ __launch_bounds__(256, 4)
void k2_stream_gemm(const float* __restrict__ la, const float* __restrict__ lb,
                    const float* __restrict__ enc,
                    const float* __restrict__ ph,
                    const float* __restrict__ W_hh, const float* __restrict__ b_hh,
                    const float* __restrict__ out_b,
                    float* __restrict__ ctx, float* __restrict__ gh,
                    float* __restrict__ d_out) {
    __shared__ __align__(16) SmemK2 s;
    const int bid = blockIdx.x;
    if (bid < 96) {
        // 4 bm tiles per block: full 32 bm x 12 bn coverage
        const int bn = (bid % 12) * 64;
        const int bm0 = (bid / 12) * 4;      // tile index base, 0..28
#pragma unroll
        for (int t = 0; t < 4; t++)
            gh_gemm_tile(s.gemm.As, s.gemm.Ws, (bm0 + t) * 64, bn, ph, W_hh, b_hh, gh);
    } else if (bid < 98) {
        int i = ((bid - 96) * 256 + threadIdx.x) * 4;
        float v = out_b[0];
        d_out[i] = v; d_out[i + 1] = v; d_out[i + 2] = v; d_out[i + 3] = v;
    } else {
        const int sb = bid - 98;      // 0..511
#pragma unroll
        for (int q = 0; q < 4; q++)
            softmax_ctx_body(s, sb + q * 512, la, lb, enc, ctx);
    }
}

// ---------------- K3: gi GEMM (3 gates, 32x64 tile) + GRU + h_new + out (R4-proven) ----------------
__global__ __launch_bounds__(256)
void k3_gru_kernel(const float* __restrict__ ctx,
                   const float* __restrict__ W_ih, const float* __restrict__ b_ih,
                   const float* __restrict__ gh,  const float* __restrict__ ph,
                   const float* __restrict__ outW, float* __restrict__ d_out) {
    __shared__ __align__(16) float As[16 * 36];
    __shared__ __align__(16) float Ws[3][16 * 68];

    const int bm = blockIdx.y * 32;
    const int bh = blockIdx.x * 64;
    const int tid = threadIdx.x;
    const int tx = tid & 15;
    const int ty = tid >> 4;

    float acc[2][4][3];
#pragma unroll
    for (int i = 0; i < 2; i++)
#pragma unroll
        for (int j = 0; j < 4; j++)
#pragma unroll
            for (int g = 0; g < 3; g++) acc[i][j][g] = 0.0f;

    for (int k0 = 0; k0 < HH; k0 += 16) {
#pragma unroll
        for (int j = 0; j < 2; j++) {
            int i = tid + 256 * j;
            int r = i >> 4, c = i & 15;
            As[c * 36 + r] = ctx[(size_t)(bm + r) * HH + k0 + c];
        }
#pragma unroll
        for (int j = 0; j < 12; j++) {
            int i = tid + 256 * j;
            int r = i >> 4, c = i & 15;
            int g = r >> 6, rr = r & 63;
            Ws[g][c * 68 + rr] = W_ih[(size_t)(g * HH + bh + rr) * HH + k0 + c];
        }
        __syncthreads();

#pragma unroll
        for (int kk = 0; kk < 16; kk++) {
            float2 a2 = *reinterpret_cast<const float2*>(&As[kk * 36 + ty * 2]);
            float av[2] = {a2.x, a2.y};
#pragma unroll
            for (int g = 0; g < 3; g++) {
                float4 w4 = *reinterpret_cast<const float4*>(&Ws[g][kk * 68 + tx * 4]);
                float wv[4] = {w4.x, w4.y, w4.z, w4.w};
#pragma unroll
                for (int i = 0; i < 2; i++)
#pragma unroll
                    for (int j = 0; j < 4; j++)
                        acc[i][j][g] = fmaf(av[i], wv[j], acc[i][j][g]);
            }
        }
        __syncthreads();
    }

#pragma unroll
    for (int i = 0; i < 2; i++) {
        const int b = bm + ty * 2 + i;
        const float* ghb = gh + (size_t)b * G3;
        float p = 0.0f;
#pragma unroll
        for (int j = 0; j < 4; j++) {
            const int h = bh + tx * 4 + j;
            float gir = acc[i][j][0] + b_ih[h];
            float giz = acc[i][j][1] + b_ih[h + 256];
            float gin = acc[i][j][2] + b_ih[h + 512];
            float r = 1.0f / (1.0f + __expf(-(gir + ghb[h])));
            float z = 1.0f / (1.0f + __expf(-(giz + ghb[h + 256])));
            float n = tanhf(gin + r * ghb[h + 512]);
            float hv = (1.0f - z) * n + z * ph[(size_t)b * HH + h];
            d_out[BB + (size_t)b * HH + h] = hv;
            p = fmaf(hv, outW[h], p);
        }
        p += __shfl_xor_sync(0xffffffffu, p, 1);
        p += __shfl_xor_sync(0xffffffffu, p, 2);
        p += __shfl_xor_sync(0xffffffffu, p, 4);
        p += __shfl_xor_sync(0xffffffffu, p, 8);
        if (tx == 0) atomicAdd(&d_out[b], p);
    }
}

// ---------------- launcher ----------------
extern "C" void kernel_launch(void* const* d_in, const int* in_sizes, int n_in,
                              void* d_out, int out_size) {
    const float* enc    = (const float*)d_in[0];
    const float* ph     = (const float*)d_in[1];
    const float* y      = (const float*)d_in[2];
    const float* attn_W = (const float*)d_in[3];
    const float* attn_b = (const float*)d_in[4];
    const float* W_ih   = (const float*)d_in[5];
    const float* W_hh   = (const float*)d_in[6];
    const float* b_ih   = (const float*)d_in[7];
    const float* b_hh   = (const float*)d_in[8];
    const float* out_W  = (const float*)d_in[9];
    const float* out_b  = (const float*)d_in[10];
    float* out = (float*)d_out;

    float *la = nullptr, *lbuf = nullptr, *ctx = nullptr, *gh = nullptr;
    cudaGetSymbolAddress((void**)&la,   g_logits_a);
    cudaGetSymbolAddress((void**)&lbuf, g_logits_b);
    cudaGetSymbolAddress((void**)&ctx,  g_ctx);
    cudaGetSymbolAddress((void**)&gh,   g_gh);

    k1_logits<<<512, 256>>>(ph, y, attn_W, attn_b, la, lbuf);
    k2_stream_gemm<<<610, 256>>>(la, lbuf, enc, ph, W_hh, b_hh, out_b, ctx, gh, out);
    k3_gru_kernel<<<dim3(4, 64), 256>>>(ctx, W_ih, b_ih, gh, ph, out_W, out);
}

// round 12
// speedup vs baseline: 1.1713x; 1.0849x over previous
#include <cuda_runtime.h>
#include <math.h>

#define BB 2048
#define SS 512
#define HH 256
#define FF 64
#define G3 (3 * HH)    // 768

// ---------------- scratch ----------------
__device__ float g_logits_a[BB * SS];  // partial logits K 0..159 (+bias)
__device__ float g_logits_b[BB * SS];  // partial logits K 160..319
__device__ float g_ctx[BB * HH];
__device__ float g_gh[BB * G3];

// ---------------- K1: split-K logits GEMM, 128x64 tiles, 8x4 microtile (256 blocks) ----------------
// bid>>7 selects K-half (0: k 0..159 -> la (+bias); 1: k 160..319 -> lb).
__global__ __launch_bounds__(256)
void k1_logits(const float* __restrict__ ph, const float* __restrict__ y,
               const float* __restrict__ attn_W, const float* __restrict__ attn_b,
               float* __restrict__ la, float* __restrict__ lb) {
    __shared__ __align__(16) float As[16 * 132];   // [c][r], 128 rows + pad
    __shared__ __align__(16) float Ws[16 * 68];    // [c][r], 64 rows + pad

    const int half = blockIdx.x >> 7;
    const int idx = blockIdx.x & 127;
    const int bm = (idx >> 3) << 7;      // 0..1920, step 128
    const int bn = (idx & 7) << 6;       // 0..448, step 64
    const int kbase = half * 160;
    const int tid = threadIdx.x;
    const int tx = tid & 15;             // N quad
    const int ty = tid >> 4;             // M oct

    float acc[8][4];
#pragma unroll
    for (int i = 0; i < 8; i++)
#pragma unroll
        for (int j = 0; j < 4; j++) acc[i][j] = 0.0f;

    for (int k0 = 0; k0 < 160; k0 += 16) {
#pragma unroll
        for (int j = 0; j < 8; j++) {          // As: 128x16
            int i = tid + 256 * j;
            int r = i >> 4, c = i & 15;
            int k = kbase + k0 + c;
            As[c * 132 + r] = (k < 256) ? ph[(size_t)(bm + r) * 256 + k]
                                        : y[(size_t)(bm + r) * 64 + (k - 256)];
        }
#pragma unroll
        for (int j = 0; j < 4; j++) {          // Ws: 64x16
            int i = tid + 256 * j;
            int r = i >> 4, c = i & 15;
            Ws[c * 68 + r] = attn_W[(size_t)(bn + r) * 320 + kbase + k0 + c];
        }
        __syncthreads();

#pragma unroll
        for (int kk = 0; kk < 16; kk++) {
            float4 a0 = *reinterpret_cast<const float4*>(&As[kk * 132 + ty * 8]);
            float4 a1 = *reinterpret_cast<const float4*>(&As[kk * 132 + ty * 8 + 4]);
            float4 w4 = *reinterpret_cast<const float4*>(&Ws[kk * 68 + tx * 4]);
            float av[8] = {a0.x, a0.y, a0.z, a0.w, a1.x, a1.y, a1.z, a1.w};
            float wv[4] = {w4.x, w4.y, w4.z, w4.w};
#pragma unroll
            for (int i = 0; i < 8; i++)
#pragma unroll
                for (int j = 0; j < 4; j++) acc[i][j] = fmaf(av[i], wv[j], acc[i][j]);
        }
        __syncthreads();
    }

    float* C = half ? lb : la;
#pragma unroll
    for (int i = 0; i < 8; i++) {
        int m = bm + ty * 8 + i;
#pragma unroll
        for (int j = 0; j < 4; j++) {
            int n = bn + tx * 4 + j;
            float b = half ? 0.0f : attn_b[n];
            C[(size_t)m * SS + n] = acc[i][j] + b;
        }
    }
}

// ---------------- K2: R9-proven, byte-identical ----------------
union SmemK2 {
    struct { float As[16 * 68]; float Ws[16 * 68]; } gemm;
    struct { float w[SS]; float red[8]; float4 part[256]; } sm;
};

__device__ __forceinline__ void gh_gemm_tile(float* __restrict__ As, float* __restrict__ Ws,
                                             int bm, int bn,
                                             const float* __restrict__ A,
                                             const float* __restrict__ W,
                                             const float* __restrict__ bias,
                                             float* __restrict__ C) {
    const int tid = threadIdx.x;
    const int tx = tid & 15;
    const int ty = tid >> 4;

    float acc[4][4];
#pragma unroll
    for (int i = 0; i < 4; i++)
#pragma unroll
        for (int j = 0; j < 4; j++) acc[i][j] = 0.0f;

    for (int k0 = 0; k0 < 256; k0 += 16) {
#pragma unroll
        for (int j = 0; j < 4; j++) {
            int i = tid + 256 * j;
            int r = i >> 4, c = i & 15;
            As[c * 68 + r] = A[(size_t)(bm + r) * 256 + k0 + c];
            Ws[c * 68 + r] = W[(size_t)(bn + r) * 256 + k0 + c];
        }
        __syncthreads();

#pragma unroll
        for (int kk = 0; kk < 16; kk++) {
            float4 a4 = *reinterpret_cast<const float4*>(&As[kk * 68 + ty * 4]);
            float4 w4 = *reinterpret_cast<const float4*>(&Ws[kk * 68 + tx * 4]);
            float av[4] = {a4.x, a4.y, a4.z, a4.w};
            float wv[4] = {w4.x, w4.y, w4.z, w4.w};
#pragma unroll
            for (int i = 0; i < 4; i++)
#pragma unroll
                for (int j = 0; j < 4; j++) acc[i][j] = fmaf(av[i], wv[j], acc[i][j]);
        }
        __syncthreads();
    }

#pragma unroll
    for (int i = 0; i < 4; i++) {
        int m = bm + ty * 4 + i;
#pragma unroll
        for (int j = 0; j < 4; j++) {
            int n = bn + tx * 4 + j;
            C[(size_t)m * G3 + n] = acc[i][j] + bias[n];
        }
    }
}

__device__ __forceinline__ void softmax_ctx_body(SmemK2& s, int b,
                                                 const float* __restrict__ la,
                                                 const float* __restrict__ lb,
                                                 const float* __restrict__ enc,
                                                 float* __restrict__ ctx) {
    const int t = threadIdx.x;

    float v0 = la[(size_t)b * SS + t]       + lb[(size_t)b * SS + t];
    float v1 = la[(size_t)b * SS + 256 + t] + lb[(size_t)b * SS + 256 + t];

    float mx = fmaxf(v0, v1);
#pragma unroll
    for (int o = 16; o; o >>= 1) mx = fmaxf(mx, __shfl_xor_sync(0xffffffffu, mx, o));
    if ((t & 31) == 0) s.sm.red[t >> 5] = mx;
    __syncthreads();
    mx = fmaxf(fmaxf(fmaxf(s.sm.red[0], s.sm.red[1]), fmaxf(s.sm.red[2], s.sm.red[3])),
               fmaxf(fmaxf(s.sm.red[4], s.sm.red[5]), fmaxf(s.sm.red[6], s.sm.red[7])));
    __syncthreads();

    float e0 = __expf(v0 - mx);
    float e1 = __expf(v1 - mx);
    s.sm.w[t] = e0;
    s.sm.w[t + 256] = e1;

    float smv = e0 + e1;
#pragma unroll
    for (int o = 16; o; o >>= 1) smv += __shfl_xor_sync(0xffffffffu, smv, o);
    if ((t & 31) == 0) s.sm.red[t >> 5] = smv;
    __syncthreads();
    float inv = 1.0f / (s.sm.red[0] + s.sm.red[1] + s.sm.red[2] + s.sm.red[3] +
                        s.sm.red[4] + s.sm.red[5] + s.sm.red[6] + s.sm.red[7]);

    const float4* ep = reinterpret_cast<const float4*>(enc + (size_t)b * SS * HH);
    const int hq = t & 63;
    const int sr = t >> 6;
    float4 acc = make_float4(0.f, 0.f, 0.f, 0.f);

    for (int s0 = 0; s0 < SS; s0 += 32) {
#pragma unroll
        for (int u = 0; u < 8; u++) {
            int row = s0 + u * 4 + sr;
            float4 v = __ldcs(&ep[(size_t)row * 64 + hq]);
            float ww = s.sm.w[row];
            acc.x = fmaf(ww, v.x, acc.x);
            acc.y = fmaf(ww, v.y, acc.y);
            acc.z = fmaf(ww, v.z, acc.z);
            acc.w = fmaf(ww, v.w, acc.w);
        }
    }

    s.sm.part[t] = acc;
    __syncthreads();
    if (t < 64) {
        float4 a = s.sm.part[t], b4 = s.sm.part[t + 64];
        float4 c4 = s.sm.part[t + 128], d4 = s.sm.part[t + 192];
        float4 r;
        r.x = (a.x + b4.x + c4.x + d4.x) * inv;
        r.y = (a.y + b4.y + c4.y + d4.y) * inv;
        r.z = (a.z + b4.z + c4.z + d4.z) * inv;
        r.w = (a.w + b4.w + c4.w + d4.w) * inv;
        *reinterpret_cast<float4*>(&ctx[(size_t)b * HH + t * 4]) = r;
    }
    __syncthreads();
}

__global__ __launch_bounds__(256, 4)
void k2_stream_gemm(const float* __restrict__ la, const float* __restrict__ lb,
                    const float* __restrict__ enc,
                    const float* __restrict__ ph,
                    const float* __restrict__ W_hh, const float* __restrict__ b_hh,
                    const float* __restrict__ out_b,
                    float* __restrict__ ctx, float* __restrict__ gh,
                    float* __restrict__ d_out) {
    __shared__ __align__(16) SmemK2 s;
    const int bid = blockIdx.x;
    if (bid < 96) {
        const int bn = (bid % 12) * 64;
        const int bm0 = (bid / 12) * 4;
#pragma unroll
        for (int t = 0; t < 4; t++)
            gh_gemm_tile(s.gemm.As, s.gemm.Ws, (bm0 + t) * 64, bn, ph, W_hh, b_hh, gh);
    } else if (bid < 98) {
        int i = ((bid - 96) * 256 + threadIdx.x) * 4;
        float v = out_b[0];
        d_out[i] = v; d_out[i + 1] = v; d_out[i + 2] = v; d_out[i + 3] = v;
    } else {
        const int sb = bid - 98;
#pragma unroll
        for (int q = 0; q < 4; q++)
            softmax_ctx_body(s, sb + q * 512, la, lb, enc, ctx);
    }
}

// ---------------- K3: gi GEMM (3 gates, 64x32 tile, 4x2 microtile) + GRU + out ----------------
// grid(8, 32): x = hidden tile (32 of 256), y = batch tile (64 of 2048). 256 threads.
__global__ __launch_bounds__(256)
void k3_gru_kernel(const float* __restrict__ ctx,
                   const float* __restrict__ W_ih, const float* __restrict__ b_ih,
                   const float* __restrict__ gh,  const float* __restrict__ ph,
                   const float* __restrict__ outW, float* __restrict__ d_out) {
    __shared__ __align__(16) float As[16 * 68];        // ctx tile [k][b], 64 rows + pad
    __shared__ __align__(16) float Ws[3 * 16 * 36];    // W_ih per gate [k][h], 32 rows + pad

    const int bm = blockIdx.y * 64;   // batch base
    const int bh = blockIdx.x * 32;   // hidden base
    const int tid = threadIdx.x;
    const int tx = tid & 15;          // hidden pair
    const int ty = tid >> 4;          // batch quad

    float acc[4][2][3];
#pragma unroll
    for (int i = 0; i < 4; i++)
#pragma unroll
        for (int j = 0; j < 2; j++)
#pragma unroll
            for (int g = 0; g < 3; g++) acc[i][j][g] = 0.0f;

    for (int k0 = 0; k0 < HH; k0 += 16) {
#pragma unroll
        for (int j = 0; j < 4; j++) {           // As: 64x16
            int i = tid + 256 * j;
            int r = i >> 4, c = i & 15;
            As[c * 68 + r] = ctx[(size_t)(bm + r) * HH + k0 + c];
        }
#pragma unroll
        for (int j = 0; j < 6; j++) {           // Ws: 3 x 32 x 16
            int i = tid + 256 * j;
            int r = i >> 4, c = i & 15;         // r: 0..95
            int g = r >> 5, rr = r & 31;
            Ws[g * 576 + c * 36 + rr] = W_ih[(size_t)(g * HH + bh + rr) * HH + k0 + c];
        }
        __syncthreads();

#pragma unroll
        for (int kk = 0; kk < 16; kk++) {
            float4 a4 = *reinterpret_cast<const float4*>(&As[kk * 68 + ty * 4]);
            float av[4] = {a4.x, a4.y, a4.z, a4.w};
#pragma unroll
            for (int g = 0; g < 3; g++) {
                float2 w2 = *reinterpret_cast<const float2*>(&Ws[g * 576 + kk * 36 + tx * 2]);
                float wv[2] = {w2.x, w2.y};
#pragma unroll
                for (int i = 0; i < 4; i++)
#pragma unroll
                    for (int j = 0; j < 2; j++)
                        acc[i][j][g] = fmaf(av[i], wv[j], acc[i][j][g]);
            }
        }
        __syncthreads();
    }

    // epilogue: gates, h_new, out projection
#pragma unroll
    for (int i = 0; i < 4; i++) {
        const int b = bm + ty * 4 + i;
        const float* ghb = gh + (size_t)b * G3;
        float p = 0.0f;
#pragma unroll
        for (int j = 0; j < 2; j++) {
            const int h = bh + tx * 2 + j;
            float gir = acc[i][j][0] + b_ih[h];
            float giz = acc[i][j][1] + b_ih[h + 256];
            float gin = acc[i][j][2] + b_ih[h + 512];
            float r = 1.0f / (1.0f + __expf(-(gir + ghb[h])));
            float z = 1.0f / (1.0f + __expf(-(giz + ghb[h + 256])));
            float n = tanhf(gin + r * ghb[h + 512]);
            float hv = (1.0f - z) * n + z * ph[(size_t)b * HH + h];
            d_out[BB + (size_t)b * HH + h] = hv;
            p = fmaf(hv, outW[h], p);
        }
        // reduce across the 16 tx lanes sharing this batch row
        p += __shfl_xor_sync(0xffffffffu, p, 1);
        p += __shfl_xor_sync(0xffffffffu, p, 2);
        p += __shfl_xor_sync(0xffffffffu, p, 4);
        p += __shfl_xor_sync(0xffffffffu, p, 8);
        if (tx == 0) atomicAdd(&d_out[b], p);
    }
}

// ---------------- launcher ----------------
extern "C" void kernel_launch(void* const* d_in, const int* in_sizes, int n_in,
                              void* d_out, int out_size) {
    const float* enc    = (const float*)d_in[0];
    const float* ph     = (const float*)d_in[1];
    const float* y      = (const float*)d_in[2];
    const float* attn_W = (const float*)d_in[3];
    const float* attn_b = (const float*)d_in[4];
    const float* W_ih   = (const float*)d_in[5];
    const float* W_hh   = (const float*)d_in[6];
    const float* b_ih   = (const float*)d_in[7];
    const float* b_hh   = (const float*)d_in[8];
    const float* out_W  = (const float*)d_in[9];
    const float* out_b  = (const float*)d_in[10];
    float* out = (float*)d_out;

    float *la = nullptr, *lbuf = nullptr, *ctx = nullptr, *gh = nullptr;
    cudaGetSymbolAddress((void**)&la,   g_logits_a);
    cudaGetSymbolAddress((void**)&lbuf, g_logits_b);
    cudaGetSymbolAddress((void**)&ctx,  g_ctx);
    cudaGetSymbolAddress((void**)&gh,   g_gh);

    k1_logits<<<256, 256>>>(ph, y, attn_W, attn_b, la, lbuf);
    k2_stream_gemm<<<610, 256>>>(la, lbuf, enc, ph, W_hh, b_hh, out_b, ctx, gh, out);
    k3_gru_kernel<<<dim3(8, 32), 256>>>(ctx, W_ih, b_ih, gh, ph, out_W, out);
}